// round 7
// baseline (speedup 1.0000x reference)
#include <cuda_runtime.h>

// Batched Kalman step: B=131072, STATE=16, OBS=8.
// 16 lanes per batch element (2 batches per warp), 8 batches per 128-thread block.
// Lane t owns state index t: cov row t and F row t live in registers.
// Packed f32x2 FMA for all 16-wide inner products.

using ull = unsigned long long;

__device__ __forceinline__ ull pk2(float lo, float hi) {
    ull r; asm("mov.b64 %0, {%1,%2};" : "=l"(r) : "f"(lo), "f"(hi)); return r;
}
__device__ __forceinline__ ull pk1(float x) {
    ull r; asm("mov.b64 %0, {%1,%1};" : "=l"(r) : "f"(x)); return r;
}
__device__ __forceinline__ void upk(ull v, float& lo, float& hi) {
    asm("mov.b64 {%0,%1}, %2;" : "=f"(lo), "=f"(hi) : "l"(v));
}
__device__ __forceinline__ ull ffma2(ull a, ull b, ull c) {
    ull d; asm("fma.rn.f32x2 %0, %1, %2, %3;" : "=l"(d) : "l"(a), "l"(b), "l"(c)); return d;
}

static constexpr int GB  = 8;        // batches per block
static constexpr int TPB = GB * 16;  // 128 threads
// Per-batch smem layout (floats). Stride 784 = 16 mod 32 banks, so the two
// half-warp batches in a warp hit disjoint bank sets on broadcast reads.
static constexpr int SB    = 784;
static constexpr int HT    = 0;    // ht[s*12+o] = H[o][s]          (192)
static constexpr int WT    = 192;  // wt[o*18+s] = (H P)[o][s]      (144)
static constexpr int SS    = 336;  // S[8][8]                       (64)
static constexpr int FT    = 400;  // ft[u*20+s] = F[s][u]          (320)
static constexpr int SMEAN = 720;  // mean[16]
static constexpr int SRES  = 736;  // resid[8]
static constexpr int SNM   = 744;  // new_mean[16]
static constexpr int NCB   = 0;    // nc[u*20+s] (320) overlays HT/WT/SS after they die

__global__ void __launch_bounds__(TPB) kf_step(
    const float* __restrict__ gin,  const float* __restrict__ gmean,
    const float* __restrict__ gcov, const float* __restrict__ gH,
    const float* __restrict__ gR,   const float* __restrict__ gF,
    const float* __restrict__ gQ,
    float* __restrict__ omean, float* __restrict__ ocov, int nb)
{
    __shared__ __align__(16) float sm[GB * SB];
    const int g = threadIdx.x >> 4;
    const int t = threadIdx.x & 15;
    const long long b = (long long)blockIdx.x * GB + g;
    if (b >= nb) return;
    float* S = sm + g * SB;

    // ---- loads: cov row t and F row t into registers ----
    float c[16], f[16];
    const float4* P4 = reinterpret_cast<const float4*>(gcov + b * 256) + t * 4;
    const float4* F4 = reinterpret_cast<const float4*>(gF   + b * 256) + t * 4;
#pragma unroll
    for (int k = 0; k < 4; k++) {
        float4 v = P4[k];
        c[4*k] = v.x; c[4*k+1] = v.y; c[4*k+2] = v.z; c[4*k+3] = v.w;
    }
#pragma unroll
    for (int k = 0; k < 4; k++) {
        float4 v = F4[k];
        f[4*k] = v.x; f[4*k+1] = v.y; f[4*k+2] = v.z; f[4*k+3] = v.w;
    }
    // H column t -> ht[s=t][o]  (coalesced per o-row across lanes)
    const float* Hb = gH + b * 128;
#pragma unroll
    for (int o = 0; o < 8; o++) S[HT + t * 12 + o] = Hb[o * 16 + t];
    // F^T: ft[u][t] = F[t][u]
#pragma unroll
    for (int u = 0; u < 16; u++) S[FT + u * 20 + t] = f[u];
    const float m = gmean[b * 16 + t];
    S[SMEAN + t] = m;
    __syncwarp();

    // ---- phase 1: PHt row t : pht[o] = sum_s c[s] * H[o][s]  (packed over o) ----
    ull ph[4];
#pragma unroll
    for (int p = 0; p < 4; p++) ph[p] = 0ull;
#pragma unroll
    for (int s = 0; s < 16; s++) {
        ull cs = pk1(c[s]);
        const ull* hr = reinterpret_cast<const ull*>(&S[HT + s * 12]);
#pragma unroll
        for (int p = 0; p < 4; p++) ph[p] = ffma2(hr[p], cs, ph[p]);
    }
    float pht[8];
#pragma unroll
    for (int p = 0; p < 4; p++) upk(ph[p], pht[2*p], pht[2*p+1]);
#pragma unroll
    for (int o = 0; o < 8; o++) S[WT + o * 18 + t] = pht[o];
    __syncwarp();

    // ---- phase 2: S = H*(PHt) + R ; lane t computes row i=t&7, cols jg*4..jg*4+3 ----
    {
        const int i = t & 7, jg = t >> 3;
        float4 rv = *reinterpret_cast<const float4*>(gR + b * 64 + i * 8 + jg * 4);
        float sv[4] = {rv.x, rv.y, rv.z, rv.w};
#pragma unroll
        for (int s = 0; s < 16; s++) {
            float hi_ = S[HT + s * 12 + i];
#pragma unroll
            for (int jj = 0; jj < 4; jj++)
                sv[jj] += hi_ * S[WT + (jg * 4 + jj) * 18 + s];
        }
        *reinterpret_cast<float4*>(&S[SS + i * 8 + jg * 4]) =
            make_float4(sv[0], sv[1], sv[2], sv[3]);
    }
    __syncwarp();

    // ---- phase 3: redundant per-lane Cholesky of S (8x8), rsqrt-based ----
    float L[28], dinv[8];  // off-diag L(i,j), j<i at i*(i-1)/2+j
#pragma unroll
    for (int j = 0; j < 8; j++) {
        float d = S[SS + j * 8 + j];
#pragma unroll
        for (int k = 0; k < j; k++) d -= L[j*(j-1)/2 + k] * L[j*(j-1)/2 + k];
        float inv = rsqrtf(d);
        dinv[j] = inv;
#pragma unroll
        for (int i2 = j + 1; i2 < 8; i2++) {
            float e = S[SS + i2 * 8 + j];
#pragma unroll
            for (int k = 0; k < j; k++) e -= L[i2*(i2-1)/2 + k] * L[j*(j-1)/2 + k];
            L[i2*(i2-1)/2 + j] = e * inv;
        }
    }
    // solve S * Krow^T = pht  (L L^T x = pht), per-lane RHS
    float y[8], K[8];
#pragma unroll
    for (int j = 0; j < 8; j++) {
        float e = pht[j];
#pragma unroll
        for (int k = 0; k < j; k++) e -= L[j*(j-1)/2 + k] * y[k];
        y[j] = e * dinv[j];
    }
#pragma unroll
    for (int j = 7; j >= 0; j--) {
        float e = y[j];
#pragma unroll
        for (int k = j + 1; k < 8; k++) e -= L[k*(k-1)/2 + j] * K[k];
        K[j] = e * dinv[j];
    }

    // ---- resid (lanes 0..7): r[o] = in[o] - sum_s H[o][s]*mean[s] ----
    if (t < 8) {
        float e = gin[b * 8 + t];
#pragma unroll
        for (int s = 0; s < 16; s++) e -= S[HT + s * 12 + t] * S[SMEAN + s];
        S[SRES + t] = e;
    }
    __syncwarp();

    // ---- new_mean[t] = mean[t] + K . resid ----
    float nm = m;
#pragma unroll
    for (int o = 0; o < 8; o++) nm += K[o] * S[SRES + o];
    S[SNM + t] = nm;

    // ---- phase 6: new_cov row t = c - K . WT  (packed over s) ----
    ull ncv[8];
#pragma unroll
    for (int p = 0; p < 8; p++) ncv[p] = pk2(c[2*p], c[2*p+1]);
#pragma unroll
    for (int o = 0; o < 8; o++) {
        ull nk = pk1(-K[o]);
        const ull* wr = reinterpret_cast<const ull*>(&S[WT + o * 18]);
#pragma unroll
        for (int p = 0; p < 8; p++) ncv[p] = ffma2(wr[p], nk, ncv[p]);
    }
    __syncwarp();  // all lanes done reading HT/WT/SS before overlay write
    {
        ull* nr = reinterpret_cast<ull*>(&S[NCB + t * 20]);
#pragma unroll
        for (int p = 0; p < 8; p++) nr[p] = ncv[p];
    }
    __syncwarp();

    // ---- phase 7: tmp[s] = sum_u f[u] * NC[u][s]  (packed over s) ----
    ull tp[8];
#pragma unroll
    for (int p = 0; p < 8; p++) tp[p] = 0ull;
#pragma unroll
    for (int u = 0; u < 16; u++) {
        ull fu = pk1(f[u]);
        const ull* nr = reinterpret_cast<const ull*>(&S[NCB + u * 20]);
#pragma unroll
        for (int p = 0; p < 8; p++) tp[p] = ffma2(nr[p], fu, tp[p]);
    }
    float tm[16];
#pragma unroll
    for (int p = 0; p < 8; p++) upk(tp[p], tm[2*p], tm[2*p+1]);

    // ---- phase 8: pred_cov row t = Q row + sum_u tm[u] * Ft[u][:]  (packed) ----
    ull pc[8];
    const float4* Q4 = reinterpret_cast<const float4*>(gQ + b * 256) + t * 4;
#pragma unroll
    for (int k = 0; k < 4; k++) {
        float4 q = Q4[k];
        pc[2*k]   = pk2(q.x, q.y);
        pc[2*k+1] = pk2(q.z, q.w);
    }
#pragma unroll
    for (int u = 0; u < 16; u++) {
        ull tu = pk1(tm[u]);
        const ull* fr = reinterpret_cast<const ull*>(&S[FT + u * 20]);
#pragma unroll
        for (int p = 0; p < 8; p++) pc[p] = ffma2(fr[p], tu, pc[p]);
    }

    // ---- pred_mean[t] = F row t . new_mean ----
    float pm = 0.f;
#pragma unroll
    for (int u = 0; u < 16; u++) pm += f[u] * S[SNM + u];
    omean[b * 16 + t] = pm;

    ull* oc = reinterpret_cast<ull*>(ocov + b * 256 + t * 16);
#pragma unroll
    for (int p = 0; p < 8; p++) oc[p] = pc[p];
}

extern "C" void kernel_launch(void* const* d_in, const int* in_sizes, int n_in,
                              void* d_out, int out_size)
{
    const float* gin   = (const float*)d_in[0];  // input [B,8]
    const float* gmean = (const float*)d_in[1];  // mean  [B,16]
    const float* gcov  = (const float*)d_in[2];  // cov   [B,16,16]
    const float* gH    = (const float*)d_in[3];  // H     [B,8,16]
    const float* gR    = (const float*)d_in[4];  // R     [B,8,8]
    const float* gF    = (const float*)d_in[5];  // F     [B,16,16]
    const float* gQ    = (const float*)d_in[6];  // Q     [B,16,16]

    const int nb = in_sizes[1] / 16;             // B from mean
    float* omean = (float*)d_out;                // pred_mean [B,16]
    float* ocov  = omean + (size_t)nb * 16;      // pred_cov  [B,16,16]

    const int blocks = (nb + GB - 1) / GB;
    kf_step<<<blocks, TPB>>>(gin, gmean, gcov, gH, gR, gF, gQ, omean, ocov, nb);
}

// round 8
// speedup vs baseline: 1.0873x; 1.0873x over previous
#include <cuda_runtime.h>

// Batched Kalman step: B=131072, STATE=16, OBS=8.
// 16 lanes per batch, 2 batches per warp, 8 per 128-thread block.
// All smem matrix rows stride-20 floats (80B, 16B aligned) so every row read
// is LDS.128 (ulonglong2), and the per-batch smem stride is ≡16 banks so the
// two half-warp batches never bank-conflict on broadcast reads.

using ull = unsigned long long;
using u2  = ulonglong2;

__device__ __forceinline__ ull pk2(float lo, float hi) {
    ull r; asm("mov.b64 %0, {%1,%2};" : "=l"(r) : "f"(lo), "f"(hi)); return r;
}
__device__ __forceinline__ ull pk1(float x) {
    ull r; asm("mov.b64 %0, {%1,%1};" : "=l"(r) : "f"(x)); return r;
}
__device__ __forceinline__ void upk(ull v, float& lo, float& hi) {
    asm("mov.b64 {%0,%1}, %2;" : "=f"(lo), "=f"(hi) : "l"(v));
}
__device__ __forceinline__ ull ffma2(ull a, ull b, ull c) {
    ull d; asm("fma.rn.f32x2 %0, %1, %2, %3;" : "=l"(d) : "l"(a), "l"(b), "l"(c)); return d;
}
__device__ __forceinline__ ull add2(ull a, ull b) {
    ull d; asm("add.rn.f32x2 %0, %1, %2;" : "=l"(d) : "l"(a), "l"(b)); return d;
}
__device__ __forceinline__ float hsum(ull a) {
    float lo, hi; upk(a, lo, hi); return lo + hi;
}

static constexpr int GB  = 8;
static constexpr int TPB = GB * 16;
// Per-batch smem layout (floats). SB ≡ 16 (mod 32 banks).
static constexpr int SB    = 912;
static constexpr int HT    = 0;    // ht[s*20+o] = H[o][s]      16 rows (320)
static constexpr int WT    = 320;  // wt[o*20+s] = (H P)[o][s]   8 rows (160)
static constexpr int SS    = 480;  // S[8][8]                            (64)
static constexpr int FT    = 544;  // ft[u*20+s] = F[s][u]      16 rows (320)
static constexpr int SMEAN = 864;  // mean[16]
static constexpr int SRES  = 880;  // resid[8]
static constexpr int SNM   = 888;  // new_mean[16]
static constexpr int NCB   = 0;    // nc[u*20+s], overlays HT (dead after phase 1)

__global__ void __launch_bounds__(TPB) kf_step(
    const float* __restrict__ gin,  const float* __restrict__ gmean,
    const float* __restrict__ gcov, const float* __restrict__ gH,
    const float* __restrict__ gR,   const float* __restrict__ gF,
    const float* __restrict__ gQ,
    float* __restrict__ omean, float* __restrict__ ocov, int nb)
{
    __shared__ __align__(16) float sm[GB * SB];
    const int g = threadIdx.x >> 4;
    const int t = threadIdx.x & 15;
    long long b = (long long)blockIdx.x * GB + g;
    const bool valid = (b < nb);
    if (!valid) b = nb - 1;               // clamp; stores predicated below
    float* S = sm + g * SB;

    // ---- loads: cov row t, F row t ----
    float c[16], f[16];
    const float4* P4 = reinterpret_cast<const float4*>(gcov + b * 256) + t * 4;
    const float4* F4 = reinterpret_cast<const float4*>(gF   + b * 256) + t * 4;
#pragma unroll
    for (int k = 0; k < 4; k++) {
        float4 v = P4[k];
        c[4*k] = v.x; c[4*k+1] = v.y; c[4*k+2] = v.z; c[4*k+3] = v.w;
    }
#pragma unroll
    for (int k = 0; k < 4; k++) {
        float4 v = F4[k];
        f[4*k] = v.x; f[4*k+1] = v.y; f[4*k+2] = v.z; f[4*k+3] = v.w;
    }
    const float* Hb = gH + b * 128;
#pragma unroll
    for (int o = 0; o < 8; o++) S[HT + t * 20 + o] = Hb[o * 16 + t];  // H^T row t
#pragma unroll
    for (int u = 0; u < 16; u++) S[FT + u * 20 + t] = f[u];           // F^T
    const float m = gmean[b * 16 + t];
    S[SMEAN + t] = m;
    __syncwarp();

    // ---- phase 1: pht[o] = sum_s c[s] * H[o][s]  (packed over o) ----
    ull ph0 = 0, ph1 = 0, ph2 = 0, ph3 = 0;
#pragma unroll
    for (int s = 0; s < 16; s++) {
        ull cs = pk1(c[s]);
        u2 h0 = *reinterpret_cast<const u2*>(&S[HT + s * 20]);
        u2 h1 = *reinterpret_cast<const u2*>(&S[HT + s * 20 + 4]);
        ph0 = ffma2(h0.x, cs, ph0); ph1 = ffma2(h0.y, cs, ph1);
        ph2 = ffma2(h1.x, cs, ph2); ph3 = ffma2(h1.y, cs, ph3);
    }
    float pht[8];
    upk(ph0, pht[0], pht[1]); upk(ph1, pht[2], pht[3]);
    upk(ph2, pht[4], pht[5]); upk(ph3, pht[6], pht[7]);
#pragma unroll
    for (int o = 0; o < 8; o++) S[WT + o * 20 + t] = pht[o];
    __syncwarp();

    // ---- phase 2: S = H*(PHt)^T + R ; lane (i=t&7, jg=t>>3) does row i, 4 cols ----
    const int i = t & 7, jg = t >> 3;
    ull hp[8];  // packed H row i (reused for resid)
    {
        const float4* Hr = reinterpret_cast<const float4*>(Hb + i * 16);
#pragma unroll
        for (int k = 0; k < 4; k++) {
            float4 v = Hr[k];
            hp[2*k] = pk2(v.x, v.y); hp[2*k+1] = pk2(v.z, v.w);
        }
    }
    {
        float4 rv = *reinterpret_cast<const float4*>(gR + b * 64 + i * 8 + jg * 4);
        float sv[4];
#pragma unroll
        for (int jj = 0; jj < 4; jj++) {
            const float* wr = &S[WT + (jg * 4 + jj) * 20];
            u2 w0 = *reinterpret_cast<const u2*>(wr);
            u2 w1 = *reinterpret_cast<const u2*>(wr + 4);
            u2 w2 = *reinterpret_cast<const u2*>(wr + 8);
            u2 w3 = *reinterpret_cast<const u2*>(wr + 12);
            ull a0 = ffma2(hp[0], w0.x, 0ull);
            ull a1 = ffma2(hp[1], w0.y, 0ull);
            a0 = ffma2(hp[2], w1.x, a0); a1 = ffma2(hp[3], w1.y, a1);
            a0 = ffma2(hp[4], w2.x, a0); a1 = ffma2(hp[5], w2.y, a1);
            a0 = ffma2(hp[6], w3.x, a0); a1 = ffma2(hp[7], w3.y, a1);
            sv[jj] = hsum(add2(a0, a1));
        }
        *reinterpret_cast<float4*>(&S[SS + i * 8 + jg * 4]) =
            make_float4(sv[0] + rv.x, sv[1] + rv.y, sv[2] + rv.z, sv[3] + rv.w);
    }
    __syncwarp();

    // ---- phase 3: redundant per-lane Cholesky of S (broadcast scalar reads) ----
    float L[28], dinv[8];
#pragma unroll
    for (int j = 0; j < 8; j++) {
        float d = S[SS + j * 8 + j];
#pragma unroll
        for (int k = 0; k < j; k++) d -= L[j*(j-1)/2 + k] * L[j*(j-1)/2 + k];
        float inv = rsqrtf(d);
        dinv[j] = inv;
#pragma unroll
        for (int i2 = j + 1; i2 < 8; i2++) {
            float e = S[SS + i2 * 8 + j];
#pragma unroll
            for (int k = 0; k < j; k++) e -= L[i2*(i2-1)/2 + k] * L[j*(j-1)/2 + k];
            L[i2*(i2-1)/2 + j] = e * inv;
        }
    }
    float y[8], K[8];
#pragma unroll
    for (int j = 0; j < 8; j++) {
        float e = pht[j];
#pragma unroll
        for (int k = 0; k < j; k++) e -= L[j*(j-1)/2 + k] * y[k];
        y[j] = e * dinv[j];
    }
#pragma unroll
    for (int j = 7; j >= 0; j--) {
        float e = y[j];
#pragma unroll
        for (int k = j + 1; k < 8; k++) e -= L[k*(k-1)/2 + j] * K[k];
        K[j] = e * dinv[j];
    }

    // ---- resid (lanes 0..7): r = in - H*mean, using packed H row + mean vec ----
    if (t < 8) {
        float e = gin[b * 8 + t];
        const float* mp = &S[SMEAN];
        u2 m0 = *reinterpret_cast<const u2*>(mp);
        u2 m1 = *reinterpret_cast<const u2*>(mp + 4);
        u2 m2 = *reinterpret_cast<const u2*>(mp + 8);
        u2 m3 = *reinterpret_cast<const u2*>(mp + 12);
        ull a0 = ffma2(hp[0], m0.x, 0ull);
        ull a1 = ffma2(hp[1], m0.y, 0ull);
        a0 = ffma2(hp[2], m1.x, a0); a1 = ffma2(hp[3], m1.y, a1);
        a0 = ffma2(hp[4], m2.x, a0); a1 = ffma2(hp[5], m2.y, a1);
        a0 = ffma2(hp[6], m3.x, a0); a1 = ffma2(hp[7], m3.y, a1);
        S[SRES + t] = e - hsum(add2(a0, a1));
    }
    __syncwarp();

    // ---- new_mean[t] = mean[t] + K . resid ----
    ull kp0 = pk2(K[0], K[1]), kp1 = pk2(K[2], K[3]);
    ull kp2 = pk2(K[4], K[5]), kp3 = pk2(K[6], K[7]);
    {
        u2 r0 = *reinterpret_cast<const u2*>(&S[SRES]);
        u2 r1 = *reinterpret_cast<const u2*>(&S[SRES + 4]);
        ull a0 = ffma2(kp0, r0.x, 0ull);
        ull a1 = ffma2(kp1, r0.y, 0ull);
        a0 = ffma2(kp2, r1.x, a0); a1 = ffma2(kp3, r1.y, a1);
        S[SNM + t] = m + hsum(add2(a0, a1));
    }

    // ---- phase 6: new_cov row t = c - K . W  (packed over s) ----
    ull ncv[8];
#pragma unroll
    for (int p = 0; p < 8; p++) ncv[p] = pk2(c[2*p], c[2*p+1]);
#pragma unroll
    for (int o = 0; o < 8; o++) {
        ull nk = pk1(-K[o]);
        const float* wr = &S[WT + o * 20];
        u2 w0 = *reinterpret_cast<const u2*>(wr);
        u2 w1 = *reinterpret_cast<const u2*>(wr + 4);
        u2 w2 = *reinterpret_cast<const u2*>(wr + 8);
        u2 w3 = *reinterpret_cast<const u2*>(wr + 12);
        ncv[0] = ffma2(w0.x, nk, ncv[0]); ncv[1] = ffma2(w0.y, nk, ncv[1]);
        ncv[2] = ffma2(w1.x, nk, ncv[2]); ncv[3] = ffma2(w1.y, nk, ncv[3]);
        ncv[4] = ffma2(w2.x, nk, ncv[4]); ncv[5] = ffma2(w2.y, nk, ncv[5]);
        ncv[6] = ffma2(w3.x, nk, ncv[6]); ncv[7] = ffma2(w3.y, nk, ncv[7]);
    }
    __syncwarp();   // HT region (overlay target) long dead; ordering safety
    {
        float* nr = &S[NCB + t * 20];
        *reinterpret_cast<u2*>(nr)      = make_ulonglong2(ncv[0], ncv[1]);
        *reinterpret_cast<u2*>(nr + 4)  = make_ulonglong2(ncv[2], ncv[3]);
        *reinterpret_cast<u2*>(nr + 8)  = make_ulonglong2(ncv[4], ncv[5]);
        *reinterpret_cast<u2*>(nr + 12) = make_ulonglong2(ncv[6], ncv[7]);
    }
    __syncwarp();

    // ---- phase 7: tm[s] = sum_u f[u] * NC[u][s]  (packed over s) ----
    ull tp[8];
#pragma unroll
    for (int p = 0; p < 8; p++) tp[p] = 0ull;
#pragma unroll
    for (int u = 0; u < 16; u++) {
        ull fu = pk1(f[u]);
        const float* nr = &S[NCB + u * 20];
        u2 n0 = *reinterpret_cast<const u2*>(nr);
        u2 n1 = *reinterpret_cast<const u2*>(nr + 4);
        u2 n2 = *reinterpret_cast<const u2*>(nr + 8);
        u2 n3 = *reinterpret_cast<const u2*>(nr + 12);
        tp[0] = ffma2(n0.x, fu, tp[0]); tp[1] = ffma2(n0.y, fu, tp[1]);
        tp[2] = ffma2(n1.x, fu, tp[2]); tp[3] = ffma2(n1.y, fu, tp[3]);
        tp[4] = ffma2(n2.x, fu, tp[4]); tp[5] = ffma2(n2.y, fu, tp[5]);
        tp[6] = ffma2(n3.x, fu, tp[6]); tp[7] = ffma2(n3.y, fu, tp[7]);
    }
    float tm[16];
#pragma unroll
    for (int p = 0; p < 8; p++) upk(tp[p], tm[2*p], tm[2*p+1]);

    // ---- phase 8: pred_cov row t = Q row + sum_u tm[u] * F^T[u][:] ----
    ull pc[8];
    const float4* Q4 = reinterpret_cast<const float4*>(gQ + b * 256) + t * 4;
#pragma unroll
    for (int k = 0; k < 4; k++) {
        float4 q = Q4[k];
        pc[2*k]   = pk2(q.x, q.y);
        pc[2*k+1] = pk2(q.z, q.w);
    }
#pragma unroll
    for (int u = 0; u < 16; u++) {
        ull tu = pk1(tm[u]);
        const float* fr = &S[FT + u * 20];
        u2 f0 = *reinterpret_cast<const u2*>(fr);
        u2 f1 = *reinterpret_cast<const u2*>(fr + 4);
        u2 f2 = *reinterpret_cast<const u2*>(fr + 8);
        u2 f3 = *reinterpret_cast<const u2*>(fr + 12);
        pc[0] = ffma2(f0.x, tu, pc[0]); pc[1] = ffma2(f0.y, tu, pc[1]);
        pc[2] = ffma2(f1.x, tu, pc[2]); pc[3] = ffma2(f1.y, tu, pc[3]);
        pc[4] = ffma2(f2.x, tu, pc[4]); pc[5] = ffma2(f2.y, tu, pc[5]);
        pc[6] = ffma2(f3.x, tu, pc[6]); pc[7] = ffma2(f3.y, tu, pc[7]);
    }

    // ---- pred_mean[t] = F row t . new_mean  (packed) ----
    {
        ull fp0 = pk2(f[0], f[1]),  fp1 = pk2(f[2], f[3]);
        ull fp2 = pk2(f[4], f[5]),  fp3 = pk2(f[6], f[7]);
        ull fp4 = pk2(f[8], f[9]),  fp5 = pk2(f[10], f[11]);
        ull fp6 = pk2(f[12], f[13]), fp7 = pk2(f[14], f[15]);
        const float* np = &S[SNM];
        u2 n0 = *reinterpret_cast<const u2*>(np);
        u2 n1 = *reinterpret_cast<const u2*>(np + 4);
        u2 n2 = *reinterpret_cast<const u2*>(np + 8);
        u2 n3 = *reinterpret_cast<const u2*>(np + 12);
        ull a0 = ffma2(fp0, n0.x, 0ull);
        ull a1 = ffma2(fp1, n0.y, 0ull);
        a0 = ffma2(fp2, n1.x, a0); a1 = ffma2(fp3, n1.y, a1);
        a0 = ffma2(fp4, n2.x, a0); a1 = ffma2(fp5, n2.y, a1);
        a0 = ffma2(fp6, n3.x, a0); a1 = ffma2(fp7, n3.y, a1);
        if (valid) omean[b * 16 + t] = hsum(add2(a0, a1));
    }

    if (valid) {
        float oc[16];
#pragma unroll
        for (int p = 0; p < 8; p++) upk(pc[p], oc[2*p], oc[2*p+1]);
        float4* od = reinterpret_cast<float4*>(ocov + b * 256 + t * 16);
#pragma unroll
        for (int k = 0; k < 4; k++)
            od[k] = make_float4(oc[4*k], oc[4*k+1], oc[4*k+2], oc[4*k+3]);
    }
}

extern "C" void kernel_launch(void* const* d_in, const int* in_sizes, int n_in,
                              void* d_out, int out_size)
{
    const float* gin   = (const float*)d_in[0];
    const float* gmean = (const float*)d_in[1];
    const float* gcov  = (const float*)d_in[2];
    const float* gH    = (const float*)d_in[3];
    const float* gR    = (const float*)d_in[4];
    const float* gF    = (const float*)d_in[5];
    const float* gQ    = (const float*)d_in[6];

    const int nb = in_sizes[1] / 16;
    float* omean = (float*)d_out;
    float* ocov  = omean + (size_t)nb * 16;

    const int blocks = (nb + GB - 1) / GB;
    kf_step<<<blocks, TPB>>>(gin, gmean, gcov, gH, gR, gF, gQ, omean, ocov, nb);
}

// round 9
// speedup vs baseline: 1.4146x; 1.3010x over previous
#include <cuda_runtime.h>

// Batched Kalman step: B=131072, STATE=16, OBS=8.
// 8 lanes per batch (lane t owns state rows t and t+8), 4 batches per warp,
// 16 batches per 128-thread block. The binding resource is smem crossbar
// delivery (128B/cyc/SM): halving lanes-per-batch halves bytes delivered
// per batch for every broadcast matrix read.

using ull = unsigned long long;
using u2  = ulonglong2;

__device__ __forceinline__ ull pk2(float lo, float hi) {
    ull r; asm("mov.b64 %0, {%1,%2};" : "=l"(r) : "f"(lo), "f"(hi)); return r;
}
__device__ __forceinline__ ull pk1(float x) {
    ull r; asm("mov.b64 %0, {%1,%1};" : "=l"(r) : "f"(x)); return r;
}
__device__ __forceinline__ void upk(ull v, float& lo, float& hi) {
    asm("mov.b64 {%0,%1}, %2;" : "=f"(lo), "=f"(hi) : "l"(v));
}
__device__ __forceinline__ ull ffma2(ull a, ull b, ull c) {
    ull d; asm("fma.rn.f32x2 %0, %1, %2, %3;" : "=l"(d) : "l"(a), "l"(b), "l"(c)); return d;
}
__device__ __forceinline__ ull add2(ull a, ull b) {
    ull d; asm("add.rn.f32x2 %0, %1, %2;" : "=l"(d) : "l"(a), "l"(b)); return d;
}
__device__ __forceinline__ float hsum(ull a) {
    float lo, hi; upk(a, lo, hi); return lo + hi;
}

static constexpr int GB  = 16;       // batches per block
static constexpr int TPB = 128;      // 8 lanes per batch
// Per-batch smem layout (floats). SB ≡ 8 (mod 32 banks) -> the 4 batches in a
// warp sit on disjoint bank groups for every broadcast access.
static constexpr int SB    = 584;
static constexpr int X     = 0;    // 16 rows x stride 20: HT -> NC -> FT  (320)
static constexpr int WT    = 320;  // wt[o*20+s] = (P H^T)[s][o], 8 rows   (160)
static constexpr int SS    = 480;  // S[8][8]                               (64)
static constexpr int SMEAN = 544;  // mean[16]
static constexpr int SRES  = 560;  // resid[8]
static constexpr int SNM   = 568;  // new_mean[16]

__global__ void __launch_bounds__(TPB) kf_step(
    const float* __restrict__ gin,  const float* __restrict__ gmean,
    const float* __restrict__ gcov, const float* __restrict__ gH,
    const float* __restrict__ gR,   const float* __restrict__ gF,
    const float* __restrict__ gQ,
    float* __restrict__ omean, float* __restrict__ ocov, int nb)
{
    __shared__ __align__(16) float sm[GB * SB];
    const int g = threadIdx.x >> 3;
    const int t = threadIdx.x & 7;
    long long b = (long long)blockIdx.x * GB + g;
    const bool valid = (b < nb);
    if (!valid) b = nb - 1;
    float* S = sm + g * SB;

    // ---- loads: cov rows t,t+8 ; F rows t,t+8 ; H row t ----
    float c0[16], c1[16], f0[16], f1[16];
    {
        const float4* P4 = reinterpret_cast<const float4*>(gcov + b * 256);
        const float4* F4 = reinterpret_cast<const float4*>(gF   + b * 256);
#pragma unroll
        for (int k = 0; k < 4; k++) {
            float4 v = P4[t * 4 + k];
            c0[4*k] = v.x; c0[4*k+1] = v.y; c0[4*k+2] = v.z; c0[4*k+3] = v.w;
            float4 w = P4[(t + 8) * 4 + k];
            c1[4*k] = w.x; c1[4*k+1] = w.y; c1[4*k+2] = w.z; c1[4*k+3] = w.w;
        }
#pragma unroll
        for (int k = 0; k < 4; k++) {
            float4 v = F4[t * 4 + k];
            f0[4*k] = v.x; f0[4*k+1] = v.y; f0[4*k+2] = v.z; f0[4*k+3] = v.w;
            float4 w = F4[(t + 8) * 4 + k];
            f1[4*k] = w.x; f1[4*k+1] = w.y; f1[4*k+2] = w.z; f1[4*k+3] = w.w;
        }
    }
    const float* Hb = gH + b * 128;
    float hr[16];       // H row t (scalar), also kept packed as hp
    ull hp[8];
    {
        const float4* H4 = reinterpret_cast<const float4*>(Hb + t * 16);
#pragma unroll
        for (int k = 0; k < 4; k++) {
            float4 v = H4[k];
            hr[4*k] = v.x; hr[4*k+1] = v.y; hr[4*k+2] = v.z; hr[4*k+3] = v.w;
            hp[2*k] = pk2(v.x, v.y); hp[2*k+1] = pk2(v.z, v.w);
        }
    }
    // H^T: lane t owns H row t -> writes column o=t of every HT row s
#pragma unroll
    for (int s = 0; s < 16; s++) S[X + s * 20 + t] = hr[s];
    const float m0 = gmean[b * 16 + t];
    const float m1 = gmean[b * 16 + t + 8];
    S[SMEAN + t] = m0; S[SMEAN + t + 8] = m1;
    __syncwarp();

    // ---- phase 1: pht_r[o] = sum_s c_r[s] * H[o][s], r in {t, t+8} ----
    ull ph0[4] = {0,0,0,0}, ph1[4] = {0,0,0,0};
#pragma unroll
    for (int s = 0; s < 16; s++) {
        ull cs0 = pk1(c0[s]), cs1 = pk1(c1[s]);
        u2 hA = *reinterpret_cast<const u2*>(&S[X + s * 20]);
        u2 hB = *reinterpret_cast<const u2*>(&S[X + s * 20 + 4]);
        ph0[0] = ffma2(hA.x, cs0, ph0[0]); ph0[1] = ffma2(hA.y, cs0, ph0[1]);
        ph0[2] = ffma2(hB.x, cs0, ph0[2]); ph0[3] = ffma2(hB.y, cs0, ph0[3]);
        ph1[0] = ffma2(hA.x, cs1, ph1[0]); ph1[1] = ffma2(hA.y, cs1, ph1[1]);
        ph1[2] = ffma2(hB.x, cs1, ph1[2]); ph1[3] = ffma2(hB.y, cs1, ph1[3]);
    }
    float pht0[8], pht1[8];
#pragma unroll
    for (int p = 0; p < 4; p++) { upk(ph0[p], pht0[2*p], pht0[2*p+1]);
                                  upk(ph1[p], pht1[2*p], pht1[2*p+1]); }
#pragma unroll
    for (int o = 0; o < 8; o++) { S[WT + o * 20 + t]     = pht0[o];
                                  S[WT + o * 20 + t + 8] = pht1[o]; }
    __syncwarp();

    // ---- phase 2: S row t : S[t][j] = dot(Hrow_t, WTrow_j) + R[t][j] ----
    {
        float4 rv0 = *reinterpret_cast<const float4*>(gR + b * 64 + t * 8);
        float4 rv1 = *reinterpret_cast<const float4*>(gR + b * 64 + t * 8 + 4);
        float rr[8] = {rv0.x, rv0.y, rv0.z, rv0.w, rv1.x, rv1.y, rv1.z, rv1.w};
        float sv[8];
#pragma unroll
        for (int j = 0; j < 8; j++) {
            const float* wr = &S[WT + j * 20];
            u2 w0 = *reinterpret_cast<const u2*>(wr);
            u2 w1 = *reinterpret_cast<const u2*>(wr + 4);
            u2 w2 = *reinterpret_cast<const u2*>(wr + 8);
            u2 w3 = *reinterpret_cast<const u2*>(wr + 12);
            ull a0 = ffma2(hp[0], w0.x, 0ull);
            ull a1 = ffma2(hp[1], w0.y, 0ull);
            a0 = ffma2(hp[2], w1.x, a0); a1 = ffma2(hp[3], w1.y, a1);
            a0 = ffma2(hp[4], w2.x, a0); a1 = ffma2(hp[5], w2.y, a1);
            a0 = ffma2(hp[6], w3.x, a0); a1 = ffma2(hp[7], w3.y, a1);
            sv[j] = rr[j] + hsum(add2(a0, a1));
        }
        float4* sd = reinterpret_cast<float4*>(&S[SS + t * 8]);
        sd[0] = make_float4(sv[0], sv[1], sv[2], sv[3]);
        sd[1] = make_float4(sv[4], sv[5], sv[6], sv[7]);
    }
    __syncwarp();

    // ---- phase 3: redundant per-lane Cholesky of S; two RHS solves ----
    float L[28], dinv[8];
#pragma unroll
    for (int j = 0; j < 8; j++) {
        float d = S[SS + j * 8 + j];
#pragma unroll
        for (int k = 0; k < j; k++) d -= L[j*(j-1)/2 + k] * L[j*(j-1)/2 + k];
        float inv = rsqrtf(d);
        dinv[j] = inv;
#pragma unroll
        for (int i2 = j + 1; i2 < 8; i2++) {
            float e = S[SS + i2 * 8 + j];
#pragma unroll
            for (int k = 0; k < j; k++) e -= L[i2*(i2-1)/2 + k] * L[j*(j-1)/2 + k];
            L[i2*(i2-1)/2 + j] = e * inv;
        }
    }
    float K0[8], K1[8];
    {
        float y0[8], y1[8];
#pragma unroll
        for (int j = 0; j < 8; j++) {
            float e0 = pht0[j], e1 = pht1[j];
#pragma unroll
            for (int k = 0; k < j; k++) { e0 -= L[j*(j-1)/2 + k] * y0[k];
                                          e1 -= L[j*(j-1)/2 + k] * y1[k]; }
            y0[j] = e0 * dinv[j]; y1[j] = e1 * dinv[j];
        }
#pragma unroll
        for (int j = 7; j >= 0; j--) {
            float e0 = y0[j], e1 = y1[j];
#pragma unroll
            for (int k = j + 1; k < 8; k++) { e0 -= L[k*(k-1)/2 + j] * K0[k];
                                              e1 -= L[k*(k-1)/2 + j] * K1[k]; }
            K0[j] = e0 * dinv[j]; K1[j] = e1 * dinv[j];
        }
    }

    // ---- resid[t] = in[t] - dot(Hrow_t, mean) ----
    {
        float e = gin[b * 8 + t];
        const float* mp = &S[SMEAN];
        u2 q0 = *reinterpret_cast<const u2*>(mp);
        u2 q1 = *reinterpret_cast<const u2*>(mp + 4);
        u2 q2 = *reinterpret_cast<const u2*>(mp + 8);
        u2 q3 = *reinterpret_cast<const u2*>(mp + 12);
        ull a0 = ffma2(hp[0], q0.x, 0ull);
        ull a1 = ffma2(hp[1], q0.y, 0ull);
        a0 = ffma2(hp[2], q1.x, a0); a1 = ffma2(hp[3], q1.y, a1);
        a0 = ffma2(hp[4], q2.x, a0); a1 = ffma2(hp[5], q2.y, a1);
        a0 = ffma2(hp[6], q3.x, a0); a1 = ffma2(hp[7], q3.y, a1);
        S[SRES + t] = e - hsum(add2(a0, a1));
    }
    __syncwarp();

    // ---- new_mean rows t, t+8 ----
    {
        u2 r0 = *reinterpret_cast<const u2*>(&S[SRES]);
        u2 r1 = *reinterpret_cast<const u2*>(&S[SRES + 4]);
        ull a0 = ffma2(pk2(K0[0], K0[1]), r0.x, 0ull);
        ull a1 = ffma2(pk2(K0[2], K0[3]), r0.y, 0ull);
        a0 = ffma2(pk2(K0[4], K0[5]), r1.x, a0);
        a1 = ffma2(pk2(K0[6], K0[7]), r1.y, a1);
        S[SNM + t] = m0 + hsum(add2(a0, a1));
        ull b0 = ffma2(pk2(K1[0], K1[1]), r0.x, 0ull);
        ull b1 = ffma2(pk2(K1[2], K1[3]), r0.y, 0ull);
        b0 = ffma2(pk2(K1[4], K1[5]), r1.x, b0);
        b1 = ffma2(pk2(K1[6], K1[7]), r1.y, b1);
        S[SNM + t + 8] = m1 + hsum(add2(b0, b1));
    }

    // ---- phase 6: NC rows t,t+8 = c - K . W ----
    ull nc0[8], nc1[8];
#pragma unroll
    for (int p = 0; p < 8; p++) { nc0[p] = pk2(c0[2*p], c0[2*p+1]);
                                  nc1[p] = pk2(c1[2*p], c1[2*p+1]); }
#pragma unroll
    for (int o = 0; o < 8; o++) {
        ull k0 = pk1(-K0[o]), k1 = pk1(-K1[o]);
        const float* wr = &S[WT + o * 20];
        u2 w0 = *reinterpret_cast<const u2*>(wr);
        u2 w1 = *reinterpret_cast<const u2*>(wr + 4);
        u2 w2 = *reinterpret_cast<const u2*>(wr + 8);
        u2 w3 = *reinterpret_cast<const u2*>(wr + 12);
        nc0[0] = ffma2(w0.x, k0, nc0[0]); nc0[1] = ffma2(w0.y, k0, nc0[1]);
        nc0[2] = ffma2(w1.x, k0, nc0[2]); nc0[3] = ffma2(w1.y, k0, nc0[3]);
        nc0[4] = ffma2(w2.x, k0, nc0[4]); nc0[5] = ffma2(w2.y, k0, nc0[5]);
        nc0[6] = ffma2(w3.x, k0, nc0[6]); nc0[7] = ffma2(w3.y, k0, nc0[7]);
        nc1[0] = ffma2(w0.x, k1, nc1[0]); nc1[1] = ffma2(w0.y, k1, nc1[1]);
        nc1[2] = ffma2(w1.x, k1, nc1[2]); nc1[3] = ffma2(w1.y, k1, nc1[3]);
        nc1[4] = ffma2(w2.x, k1, nc1[4]); nc1[5] = ffma2(w2.y, k1, nc1[5]);
        nc1[6] = ffma2(w3.x, k1, nc1[6]); nc1[7] = ffma2(w3.y, k1, nc1[7]);
    }
    __syncwarp();   // all phase-1 HT reads complete before overlaying X
    {
        u2* r0 = reinterpret_cast<u2*>(&S[X + t * 20]);
        r0[0] = make_ulonglong2(nc0[0], nc0[1]);
        r0[1] = make_ulonglong2(nc0[2], nc0[3]);
        r0[2] = make_ulonglong2(nc0[4], nc0[5]);
        r0[3] = make_ulonglong2(nc0[6], nc0[7]);
        u2* r1 = reinterpret_cast<u2*>(&S[X + (t + 8) * 20]);
        r1[0] = make_ulonglong2(nc1[0], nc1[1]);
        r1[1] = make_ulonglong2(nc1[2], nc1[3]);
        r1[2] = make_ulonglong2(nc1[4], nc1[5]);
        r1[3] = make_ulonglong2(nc1[6], nc1[7]);
    }
    __syncwarp();

    // ---- phase 7: tm_r[s] = sum_u F[r][u] * NC[u][s] ----
    ull tp0[8], tp1[8];
#pragma unroll
    for (int p = 0; p < 8; p++) { tp0[p] = 0ull; tp1[p] = 0ull; }
#pragma unroll
    for (int u = 0; u < 16; u++) {
        ull fu0 = pk1(f0[u]), fu1 = pk1(f1[u]);
        const float* nr = &S[X + u * 20];
        u2 n0 = *reinterpret_cast<const u2*>(nr);
        u2 n1 = *reinterpret_cast<const u2*>(nr + 4);
        u2 n2 = *reinterpret_cast<const u2*>(nr + 8);
        u2 n3 = *reinterpret_cast<const u2*>(nr + 12);
        tp0[0] = ffma2(n0.x, fu0, tp0[0]); tp0[1] = ffma2(n0.y, fu0, tp0[1]);
        tp0[2] = ffma2(n1.x, fu0, tp0[2]); tp0[3] = ffma2(n1.y, fu0, tp0[3]);
        tp0[4] = ffma2(n2.x, fu0, tp0[4]); tp0[5] = ffma2(n2.y, fu0, tp0[5]);
        tp0[6] = ffma2(n3.x, fu0, tp0[6]); tp0[7] = ffma2(n3.y, fu0, tp0[7]);
        tp1[0] = ffma2(n0.x, fu1, tp1[0]); tp1[1] = ffma2(n0.y, fu1, tp1[1]);
        tp1[2] = ffma2(n1.x, fu1, tp1[2]); tp1[3] = ffma2(n1.y, fu1, tp1[3]);
        tp1[4] = ffma2(n2.x, fu1, tp1[4]); tp1[5] = ffma2(n2.y, fu1, tp1[5]);
        tp1[6] = ffma2(n3.x, fu1, tp1[6]); tp1[7] = ffma2(n3.y, fu1, tp1[7]);
    }
    float tm0[16], tm1[16];
#pragma unroll
    for (int p = 0; p < 8; p++) { upk(tp0[p], tm0[2*p], tm0[2*p+1]);
                                  upk(tp1[p], tm1[2*p], tm1[2*p+1]); }
    __syncwarp();   // all NC reads done before overlaying X with F^T

    // F^T into X from registers: ft[u][v] = F[v][u]; lane t writes cols t, t+8
#pragma unroll
    for (int u = 0; u < 16; u++) { S[X + u * 20 + t]     = f0[u];
                                   S[X + u * 20 + t + 8] = f1[u]; }
    __syncwarp();

    // ---- phase 8: pred_cov rows t,t+8 = Q + sum_u tm[u] * F^T[u][:] ----
    ull pc0[8], pc1[8];
    {
        const float4* Q4 = reinterpret_cast<const float4*>(gQ + b * 256);
#pragma unroll
        for (int k = 0; k < 4; k++) {
            float4 q = Q4[t * 4 + k];
            pc0[2*k] = pk2(q.x, q.y); pc0[2*k+1] = pk2(q.z, q.w);
            float4 r = Q4[(t + 8) * 4 + k];
            pc1[2*k] = pk2(r.x, r.y); pc1[2*k+1] = pk2(r.z, r.w);
        }
    }
#pragma unroll
    for (int u = 0; u < 16; u++) {
        ull tu0 = pk1(tm0[u]), tu1 = pk1(tm1[u]);
        const float* fr = &S[X + u * 20];
        u2 e0 = *reinterpret_cast<const u2*>(fr);
        u2 e1 = *reinterpret_cast<const u2*>(fr + 4);
        u2 e2 = *reinterpret_cast<const u2*>(fr + 8);
        u2 e3 = *reinterpret_cast<const u2*>(fr + 12);
        pc0[0] = ffma2(e0.x, tu0, pc0[0]); pc0[1] = ffma2(e0.y, tu0, pc0[1]);
        pc0[2] = ffma2(e1.x, tu0, pc0[2]); pc0[3] = ffma2(e1.y, tu0, pc0[3]);
        pc0[4] = ffma2(e2.x, tu0, pc0[4]); pc0[5] = ffma2(e2.y, tu0, pc0[5]);
        pc0[6] = ffma2(e3.x, tu0, pc0[6]); pc0[7] = ffma2(e3.y, tu0, pc0[7]);
        pc1[0] = ffma2(e0.x, tu1, pc1[0]); pc1[1] = ffma2(e0.y, tu1, pc1[1]);
        pc1[2] = ffma2(e1.x, tu1, pc1[2]); pc1[3] = ffma2(e1.y, tu1, pc1[3]);
        pc1[4] = ffma2(e2.x, tu1, pc1[4]); pc1[5] = ffma2(e2.y, tu1, pc1[5]);
        pc1[6] = ffma2(e3.x, tu1, pc1[6]); pc1[7] = ffma2(e3.y, tu1, pc1[7]);
    }

    // ---- pred_mean rows t, t+8 = F row . new_mean ----
    {
        const float* np = &S[SNM];
        u2 n0 = *reinterpret_cast<const u2*>(np);
        u2 n1 = *reinterpret_cast<const u2*>(np + 4);
        u2 n2 = *reinterpret_cast<const u2*>(np + 8);
        u2 n3 = *reinterpret_cast<const u2*>(np + 12);
        ull a0 = ffma2(pk2(f0[0], f0[1]),  n0.x, 0ull);
        ull a1 = ffma2(pk2(f0[2], f0[3]),  n0.y, 0ull);
        a0 = ffma2(pk2(f0[4], f0[5]),  n1.x, a0);
        a1 = ffma2(pk2(f0[6], f0[7]),  n1.y, a1);
        a0 = ffma2(pk2(f0[8], f0[9]),  n2.x, a0);
        a1 = ffma2(pk2(f0[10], f0[11]), n2.y, a1);
        a0 = ffma2(pk2(f0[12], f0[13]), n3.x, a0);
        a1 = ffma2(pk2(f0[14], f0[15]), n3.y, a1);
        ull b0 = ffma2(pk2(f1[0], f1[1]),  n0.x, 0ull);
        ull b1 = ffma2(pk2(f1[2], f1[3]),  n0.y, 0ull);
        b0 = ffma2(pk2(f1[4], f1[5]),  n1.x, b0);
        b1 = ffma2(pk2(f1[6], f1[7]),  n1.y, b1);
        b0 = ffma2(pk2(f1[8], f1[9]),  n2.x, b0);
        b1 = ffma2(pk2(f1[10], f1[11]), n2.y, b1);
        b0 = ffma2(pk2(f1[12], f1[13]), n3.x, b0);
        b1 = ffma2(pk2(f1[14], f1[15]), n3.y, b1);
        if (valid) {
            omean[b * 16 + t]     = hsum(add2(a0, a1));
            omean[b * 16 + t + 8] = hsum(add2(b0, b1));
        }
    }

    if (valid) {
        float v[16];
        float4* od0 = reinterpret_cast<float4*>(ocov + b * 256 + t * 16);
#pragma unroll
        for (int p = 0; p < 8; p++) upk(pc0[p], v[2*p], v[2*p+1]);
#pragma unroll
        for (int k = 0; k < 4; k++)
            od0[k] = make_float4(v[4*k], v[4*k+1], v[4*k+2], v[4*k+3]);
        float4* od1 = reinterpret_cast<float4*>(ocov + b * 256 + (t + 8) * 16);
#pragma unroll
        for (int p = 0; p < 8; p++) upk(pc1[p], v[2*p], v[2*p+1]);
#pragma unroll
        for (int k = 0; k < 4; k++)
            od1[k] = make_float4(v[4*k], v[4*k+1], v[4*k+2], v[4*k+3]);
    }
}

extern "C" void kernel_launch(void* const* d_in, const int* in_sizes, int n_in,
                              void* d_out, int out_size)
{
    const float* gin   = (const float*)d_in[0];
    const float* gmean = (const float*)d_in[1];
    const float* gcov  = (const float*)d_in[2];
    const float* gH    = (const float*)d_in[3];
    const float* gR    = (const float*)d_in[4];
    const float* gF    = (const float*)d_in[5];
    const float* gQ    = (const float*)d_in[6];

    const int nb = in_sizes[1] / 16;
    float* omean = (float*)d_out;
    float* ocov  = omean + (size_t)nb * 16;

    const int blocks = (nb + GB - 1) / GB;
    kf_step<<<blocks, TPB>>>(gin, gmean, gcov, gH, gR, gF, gQ, omean, ocov, nb);
}